// round 1
// baseline (speedup 1.0000x reference)
#include <cuda_runtime.h>
#include <cstddef>

// Problem constants
#define Bb 8
#define Np 8192
#define Mp 1024
#define Cc 256
#define Rr (Bb*Np)       // 65536 rows
#define BN_EPS 1e-5f

// Scratch (static __device__ — no allocations allowed)
__device__ float g_bufA[(size_t)Rr*Cc];     // 64 MB
__device__ float g_bufB[(size_t)Rr*Cc];     // 64 MB
__device__ float g_xT[(size_t)Bb*Mp*Cc];    // 8 MB
__device__ float g_sum[Cc];
__device__ float g_sumsq[Cc];
__device__ float g_scale[Cc];
__device__ float g_shift[Cc];

// ---------------------------------------------------------------------------
// zero stats
__global__ void zero_stats_kernel() {
    int t = threadIdx.x;
    g_sum[t] = 0.f; g_sumsq[t] = 0.f;
}

// ---------------------------------------------------------------------------
// transpose x[b][c][m] -> xT[b][m][c]
__global__ void transpose_x_kernel(const float* __restrict__ x, float* __restrict__ xT) {
    __shared__ float t[32][33];
    int b = blockIdx.z;
    int m0 = blockIdx.x * 32, c0 = blockIdx.y * 32;
    int tx = threadIdx.x, ty = threadIdx.y; // 32 x 8
    const float* xb = x + (size_t)b * Cc * Mp;
    #pragma unroll
    for (int k = 0; k < 32; k += 8)
        t[ty + k][tx] = xb[(size_t)(c0 + ty + k) * Mp + m0 + tx];
    __syncthreads();
    float* ob = xT + (size_t)b * Mp * Cc;
    #pragma unroll
    for (int k = 0; k < 32; k += 8)
        ob[(size_t)(m0 + ty + k) * Cc + c0 + tx] = t[tx][ty + k];
}

// ---------------------------------------------------------------------------
// 3-NN (matching the reference's d2 = |p|^2 + |q|^2 - 2 p.q expansion) +
// inverse-distance-weighted feature interpolation.
// grid (Bb, Np/128), block 128. Writes h0 in [b][n][c] layout (n-major).
__global__ void knn_interp_kernel(const float* __restrict__ p,
                                  const float* __restrict__ q,
                                  const float* __restrict__ xT,
                                  float* __restrict__ h0) {
    __shared__ float sqx[Mp], sqy[Mp], sqz[Mp], sqq[Mp];
    __shared__ float sw[128][3];
    __shared__ int   si[128][3];
    const int b = blockIdx.x;
    const int n0 = blockIdx.y * 128;
    const int tid = threadIdx.x;

    for (int m = tid; m < Mp; m += 128) {
        float qx = q[((size_t)b * Mp + m) * 3 + 0];
        float qy = q[((size_t)b * Mp + m) * 3 + 1];
        float qz = q[((size_t)b * Mp + m) * 3 + 2];
        sqx[m] = qx; sqy[m] = qy; sqz[m] = qz;
        sqq[m] = qx * qx + qy * qy + qz * qz;
    }
    __syncthreads();

    const int n = n0 + tid;
    float px = p[((size_t)b * Np + n) * 3 + 0];
    float py = p[((size_t)b * Np + n) * 3 + 1];
    float pz = p[((size_t)b * Np + n) * 3 + 2];
    float pp = px * px + py * py + pz * pz;

    float d0 = 3.4e38f, d1 = 3.4e38f, d2v = 3.4e38f;
    int   i0 = 0, i1 = 0, i2 = 0;
    #pragma unroll 4
    for (int m = 0; m < Mp; m++) {
        float dot = px * sqx[m] + py * sqy[m] + pz * sqz[m];
        float d = pp + sqq[m] - 2.f * dot;
        if (d < d2v) {
            if (d < d1) {
                d2v = d1; i2 = i1;
                if (d < d0) { d1 = d0; i1 = i0; d0 = d; i0 = m; }
                else        { d1 = d;  i1 = m; }
            } else { d2v = d; i2 = m; }
        }
    }
    float a0 = 1.f / fmaxf(d0, 1e-10f);
    float a1 = 1.f / fmaxf(d1, 1e-10f);
    float a2 = 1.f / fmaxf(d2v, 1e-10f);
    float inv = 1.f / (a0 + a1 + a2);
    sw[tid][0] = a0 * inv; sw[tid][1] = a1 * inv; sw[tid][2] = a2 * inv;
    si[tid][0] = i0; si[tid][1] = i1; si[tid][2] = i2;
    __syncthreads();

    // gather phase: warp-per-point, coalesced reads of xT rows
    const int lane = tid & 31, warp = tid >> 5;
    const float* xb = xT + (size_t)b * Mp * Cc;
    for (int nl = warp * 32; nl < warp * 32 + 32; nl++) {
        float w0 = sw[nl][0], w1 = sw[nl][1], w2 = sw[nl][2];
        const float* r0 = xb + (size_t)si[nl][0] * Cc;
        const float* r1 = xb + (size_t)si[nl][1] * Cc;
        const float* r2 = xb + (size_t)si[nl][2] * Cc;
        float* o = h0 + ((size_t)b * Np + n0 + nl) * Cc;
        #pragma unroll
        for (int c = lane; c < Cc; c += 32)
            o[c] = w0 * r0[c] + w1 * r1[c] + w2 * r2[c];
    }
}

// ---------------------------------------------------------------------------
// GEMM: out[r][o] = sum_c act(in[r][c]) * W[o][c] + bias[o]
// act(v) = useAct ? relu(v*g_scale[c] + g_shift[c]) : v   (prev layer's BN+ReLU fused)
// 128x128 tile, BK=8, 256 threads, 8x8 per thread, double-buffered smem.
#define BM 128
#define BNt 128
#define BK 8

__global__ void __launch_bounds__(256)
gemm_fused_kernel(const float* __restrict__ A, const float* __restrict__ W,
                  const float* __restrict__ bias, int useAct,
                  float* __restrict__ out, int K, int O) {
    __shared__ float As[2][BK][BM];
    __shared__ float Bs[2][BK][BNt];
    const int tid = threadIdx.x;
    const int arow = tid >> 1;
    const int ak = (tid & 1) << 2;
    const size_t rowBase = (size_t)blockIdx.x * BM;
    const int colBase = blockIdx.y * BNt;
    const float* Ap = A + (rowBase + arow) * K + ak;
    const float* Wp = W + (size_t)(colBase + arow) * K + ak;

    float acc[8][8];
    #pragma unroll
    for (int i = 0; i < 8; i++)
        #pragma unroll
        for (int j = 0; j < 8; j++) acc[i][j] = 0.f;

    // prologue: tile k0 = 0 into buffer 0
    {
        float4 a = *(const float4*)Ap;
        if (useAct) {
            a.x = fmaxf(fmaf(a.x, g_scale[ak + 0], g_shift[ak + 0]), 0.f);
            a.y = fmaxf(fmaf(a.y, g_scale[ak + 1], g_shift[ak + 1]), 0.f);
            a.z = fmaxf(fmaf(a.z, g_scale[ak + 2], g_shift[ak + 2]), 0.f);
            a.w = fmaxf(fmaf(a.w, g_scale[ak + 3], g_shift[ak + 3]), 0.f);
        }
        float4 w4 = *(const float4*)Wp;
        As[0][ak + 0][arow] = a.x;  As[0][ak + 1][arow] = a.y;
        As[0][ak + 2][arow] = a.z;  As[0][ak + 3][arow] = a.w;
        Bs[0][ak + 0][arow] = w4.x; Bs[0][ak + 1][arow] = w4.y;
        Bs[0][ak + 2][arow] = w4.z; Bs[0][ak + 3][arow] = w4.w;
    }
    __syncthreads();

    const int tx = tid & 15, ty = tid >> 4;
    int buf = 0;
    for (int k0 = BK; k0 <= K; k0 += BK) {
        float4 an, wn;
        const bool more = (k0 < K);
        if (more) {
            an = *(const float4*)(Ap + k0);
            wn = *(const float4*)(Wp + k0);
            if (useAct) {
                int c = k0 + ak;
                an.x = fmaxf(fmaf(an.x, g_scale[c + 0], g_shift[c + 0]), 0.f);
                an.y = fmaxf(fmaf(an.y, g_scale[c + 1], g_shift[c + 1]), 0.f);
                an.z = fmaxf(fmaf(an.z, g_scale[c + 2], g_shift[c + 2]), 0.f);
                an.w = fmaxf(fmaf(an.w, g_scale[c + 3], g_shift[c + 3]), 0.f);
            }
        }
        #pragma unroll
        for (int k = 0; k < BK; k++) {
            float ar[8], br[8];
            #pragma unroll
            for (int i = 0; i < 8; i++) ar[i] = As[buf][k][ty * 8 + i];
            #pragma unroll
            for (int j = 0; j < 8; j++) br[j] = Bs[buf][k][tx * 8 + j];
            #pragma unroll
            for (int i = 0; i < 8; i++)
                #pragma unroll
                for (int j = 0; j < 8; j++)
                    acc[i][j] = fmaf(ar[i], br[j], acc[i][j]);
        }
        if (more) {
            int nb = buf ^ 1;
            As[nb][ak + 0][arow] = an.x;  As[nb][ak + 1][arow] = an.y;
            As[nb][ak + 2][arow] = an.z;  As[nb][ak + 3][arow] = an.w;
            Bs[nb][ak + 0][arow] = wn.x;  Bs[nb][ak + 1][arow] = wn.y;
            Bs[nb][ak + 2][arow] = wn.z;  Bs[nb][ak + 3][arow] = wn.w;
            __syncthreads();
            buf = nb;
        }
    }

    // epilogue: +bias, store (pre-BN values; stats computed by the next kernel)
    #pragma unroll
    for (int i = 0; i < 8; i++) {
        size_t r = rowBase + ty * 8 + i;
        float* op = out + r * O + colBase + tx * 8;
        #pragma unroll
        for (int j = 0; j < 8; j++) acc[i][j] += bias[colBase + tx * 8 + j];
        *(float4*)(op)     = make_float4(acc[i][0], acc[i][1], acc[i][2], acc[i][3]);
        *(float4*)(op + 4) = make_float4(acc[i][4], acc[i][5], acc[i][6], acc[i][7]);
    }
}

// ---------------------------------------------------------------------------
// per-channel sum / sumsq over the (B*N) rows. grid 256, block O (128|256).
__global__ void stats_reduce_kernel(const float* __restrict__ in, int O) {
    const int t = threadIdx.x;
    const size_t r0 = (size_t)blockIdx.x * 256;
    const float* ptr = in + r0 * O + t;
    float s = 0.f, ss = 0.f;
    #pragma unroll 8
    for (int r = 0; r < 256; r++) {
        float v = ptr[(size_t)r * O];
        s += v; ss += v * v;
    }
    atomicAdd(&g_sum[t], s);
    atomicAdd(&g_sumsq[t], ss);
}

// fold BN into per-channel affine: scale = gamma*rsqrt(var+eps), shift = beta - mu*scale
__global__ void bn_finalize_kernel(const float* __restrict__ g,
                                   const float* __restrict__ beta, int O) {
    int t = threadIdx.x; // 256 threads always
    if (t < O) {
        const float cnt = (float)Rr;
        float mu  = g_sum[t] / cnt;
        float var = fmaxf(g_sumsq[t] / cnt - mu * mu, 0.f);
        float sc  = rsqrtf(var + BN_EPS) * g[t];
        g_scale[t] = sc;
        g_shift[t] = beta[t] - mu * sc;
    }
    g_sum[t] = 0.f; g_sumsq[t] = 0.f;
}

// ---------------------------------------------------------------------------
// final BN+ReLU + transpose [b][n][o] -> [b][o][n] into d_out (O = 128)
__global__ void output_kernel(const float* __restrict__ in, float* __restrict__ out) {
    __shared__ float t[32][33];
    const int b = blockIdx.z;
    const int n0 = blockIdx.x * 32, o0 = blockIdx.y * 32;
    const int tx = threadIdx.x, ty = threadIdx.y; // 32 x 8
    #pragma unroll
    for (int k = 0; k < 32; k += 8) {
        int o = o0 + tx;
        float v = in[((size_t)b * Np + n0 + ty + k) * 128 + o];
        t[ty + k][tx] = fmaxf(fmaf(v, g_scale[o], g_shift[o]), 0.f);
    }
    __syncthreads();
    #pragma unroll
    for (int k = 0; k < 32; k += 8)
        out[((size_t)b * 128 + o0 + ty + k) * Np + n0 + tx] = t[tx][ty + k];
}

// ---------------------------------------------------------------------------
extern "C" void kernel_launch(void* const* d_in, const int* in_sizes, int n_in,
                              void* d_out, int out_size) {
    const float* p   = (const float*)d_in[0];
    const float* q   = (const float*)d_in[1];
    const float* x   = (const float*)d_in[2];
    const float* w0  = (const float*)d_in[3];
    const float* b0  = (const float*)d_in[4];
    const float* g0  = (const float*)d_in[5];
    const float* be0 = (const float*)d_in[6];
    const float* w1  = (const float*)d_in[7];
    const float* b1  = (const float*)d_in[8];
    const float* g1  = (const float*)d_in[9];
    const float* be1 = (const float*)d_in[10];
    const float* w2  = (const float*)d_in[11];
    const float* b2  = (const float*)d_in[12];
    const float* g2  = (const float*)d_in[13];
    const float* be2 = (const float*)d_in[14];
    float* out = (float*)d_out;

    float *bufA, *bufB, *xT;
    cudaGetSymbolAddress((void**)&bufA, g_bufA);
    cudaGetSymbolAddress((void**)&bufB, g_bufB);
    cudaGetSymbolAddress((void**)&xT,  g_xT);

    const int Qfloats = Bb * Mp * 3;                    // 24576
    const int Hfloats = Bb * 128 * Np;                  // 8388608
    const int qoff = (out_size >= Qfloats + Hfloats) ? Qfloats : 0;

    zero_stats_kernel<<<1, 256>>>();
    transpose_x_kernel<<<dim3(Mp / 32, Cc / 32, Bb), dim3(32, 8)>>>(x, xT);
    knn_interp_kernel<<<dim3(Bb, Np / 128), 128>>>(p, q, xT, bufA);

    // layer 0: in bufA (raw), out bufB (256 ch)
    gemm_fused_kernel<<<dim3(Rr / BM, 2), 256>>>(bufA, w0, b0, 0, bufB, Cc, 256);
    stats_reduce_kernel<<<256, 256>>>(bufB, 256);
    bn_finalize_kernel<<<1, 256>>>(g0, be0, 256);

    // layer 1: in bufB (BN0+ReLU fused on load), out bufA (256 ch)
    gemm_fused_kernel<<<dim3(Rr / BM, 2), 256>>>(bufB, w1, b1, 1, bufA, 256, 256);
    stats_reduce_kernel<<<256, 256>>>(bufA, 256);
    bn_finalize_kernel<<<1, 256>>>(g1, be1, 256);

    // layer 2: in bufA (BN1+ReLU fused on load), out bufB (128 ch)
    gemm_fused_kernel<<<dim3(Rr / BM, 1), 256>>>(bufA, w2, b2, 1, bufB, 256, 128);
    stats_reduce_kernel<<<256, 128>>>(bufB, 128);
    bn_finalize_kernel<<<1, 256>>>(g2, be2, 128);

    // output: [q | BN2+ReLU(h) transposed to [B,128,N]]
    if (qoff)
        cudaMemcpyAsync(out, q, (size_t)Qfloats * sizeof(float),
                        cudaMemcpyDeviceToDevice);
    output_kernel<<<dim3(Np / 32, 4, Bb), dim3(32, 8)>>>(bufB, out + qoff);
}

// round 4
// speedup vs baseline: 1.8658x; 1.8658x over previous
#include <cuda_runtime.h>
#include <cstddef>
#include <cstdint>

// Problem constants
#define Bb 8
#define Np 8192
#define Mp 1024
#define Cc 256
#define Rr (Bb*Np)       // 65536 rows
#define BN_EPS 1e-5f

// Scratch (static __device__ — no allocations allowed)
__device__ float g_bufA[(size_t)Rr*Cc];     // 64 MB
__device__ float g_bufB[(size_t)Rr*Cc];     // 64 MB
__device__ float g_xT[(size_t)Bb*Mp*Cc];    // 8 MB
__device__ float g_sum[Cc];
__device__ float g_sumsq[Cc];
__device__ float g_scale[Cc];
__device__ float g_shift[Cc];

// ---------------------------------------------------------------------------
__global__ void zero_stats_kernel() {
    int t = threadIdx.x;
    g_sum[t] = 0.f; g_sumsq[t] = 0.f;
}

// ---------------------------------------------------------------------------
// transpose x[b][c][m] -> xT[b][m][c]
__global__ void transpose_x_kernel(const float* __restrict__ x, float* __restrict__ xT) {
    __shared__ float t[32][33];
    int b = blockIdx.z;
    int m0 = blockIdx.x * 32, c0 = blockIdx.y * 32;
    int tx = threadIdx.x, ty = threadIdx.y; // 32 x 8
    const float* xb = x + (size_t)b * Cc * Mp;
    #pragma unroll
    for (int k = 0; k < 32; k += 8)
        t[ty + k][tx] = xb[(size_t)(c0 + ty + k) * Mp + m0 + tx];
    __syncthreads();
    float* ob = xT + (size_t)b * Mp * Cc;
    #pragma unroll
    for (int k = 0; k < 32; k += 8)
        ob[(size_t)(m0 + ty + k) * Cc + c0 + tx] = t[tx][ty + k];
}

// ---------------------------------------------------------------------------
// 3-NN + inverse-distance-weighted interpolation. Writes h0 in [b][n][c].
__global__ void knn_interp_kernel(const float* __restrict__ p,
                                  const float* __restrict__ q,
                                  const float* __restrict__ xT,
                                  float* __restrict__ h0) {
    __shared__ float sqx[Mp], sqy[Mp], sqz[Mp], sqq[Mp];
    __shared__ float sw[128][3];
    __shared__ int   si[128][3];
    const int b = blockIdx.x;
    const int n0 = blockIdx.y * 128;
    const int tid = threadIdx.x;

    for (int m = tid; m < Mp; m += 128) {
        float qx = q[((size_t)b * Mp + m) * 3 + 0];
        float qy = q[((size_t)b * Mp + m) * 3 + 1];
        float qz = q[((size_t)b * Mp + m) * 3 + 2];
        sqx[m] = qx; sqy[m] = qy; sqz[m] = qz;
        sqq[m] = qx * qx + qy * qy + qz * qz;
    }
    __syncthreads();

    const int n = n0 + tid;
    float px = p[((size_t)b * Np + n) * 3 + 0];
    float py = p[((size_t)b * Np + n) * 3 + 1];
    float pz = p[((size_t)b * Np + n) * 3 + 2];
    float pp = px * px + py * py + pz * pz;

    float d0 = 3.4e38f, d1 = 3.4e38f, d2v = 3.4e38f;
    int   i0 = 0, i1 = 0, i2 = 0;
    #pragma unroll 4
    for (int m = 0; m < Mp; m++) {
        float dot = px * sqx[m] + py * sqy[m] + pz * sqz[m];
        float d = pp + sqq[m] - 2.f * dot;
        if (d < d2v) {
            if (d < d1) {
                d2v = d1; i2 = i1;
                if (d < d0) { d1 = d0; i1 = i0; d0 = d; i0 = m; }
                else        { d1 = d;  i1 = m; }
            } else { d2v = d; i2 = m; }
        }
    }
    float a0 = 1.f / fmaxf(d0, 1e-10f);
    float a1 = 1.f / fmaxf(d1, 1e-10f);
    float a2 = 1.f / fmaxf(d2v, 1e-10f);
    float inv = 1.f / (a0 + a1 + a2);
    sw[tid][0] = a0 * inv; sw[tid][1] = a1 * inv; sw[tid][2] = a2 * inv;
    si[tid][0] = i0; si[tid][1] = i1; si[tid][2] = i2;
    __syncthreads();

    const int lane = tid & 31, warp = tid >> 5;
    const float* xb = xT + (size_t)b * Mp * Cc;
    for (int nl = warp * 32; nl < warp * 32 + 32; nl++) {
        float w0 = sw[nl][0], w1 = sw[nl][1], w2 = sw[nl][2];
        const float* r0 = xb + (size_t)si[nl][0] * Cc;
        const float* r1 = xb + (size_t)si[nl][1] * Cc;
        const float* r2 = xb + (size_t)si[nl][2] * Cc;
        float* o = h0 + ((size_t)b * Np + n0 + nl) * Cc;
        #pragma unroll
        for (int c = lane; c < Cc; c += 32)
            o[c] = w0 * r0[c] + w1 * r1[c] + w2 * r2[c];
    }
}

// ---------------------------------------------------------------------------
// tf32 mma.sync GEMM (sm_80-compatible PTX path -> legacy HMMA pipe)
// ---------------------------------------------------------------------------
__device__ __forceinline__ uint32_t f2tf32(float f) {
    uint32_t r; asm("cvt.rna.tf32.f32 %0, %1;" : "=r"(r) : "f"(f)); return r;
}

#define MMA_TF32(c, a, b) \
    asm volatile("mma.sync.aligned.m16n8k8.row.col.f32.tf32.tf32.f32 " \
        "{%0,%1,%2,%3},{%4,%5,%6,%7},{%8,%9},{%0,%1,%2,%3};" \
        : "+f"((c)[0]), "+f"((c)[1]), "+f"((c)[2]), "+f"((c)[3]) \
        : "r"((a).x), "r"((a).y), "r"((a).z), "r"((a).w), "r"((b).x), "r"((b).y))

// Fragment-packed smem layouts (units: floats)
//  A: [g = m>>4 (8)] stride 528, [kstep (4)] stride 132, [lane (32)] stride 4, [reg (4)]
//  B: [h = n>>3 (16)] stride 264, [kstep (4)] stride 66, [lane (32)] stride 2, [reg (2)]
// kstep strides carry a +4/+2 float bank skew so producer stores spread banks.
#define A_BUF_FLOATS 4224      // 8 * 528
#define B_BUF_FLOATS 4224      // 16 * 264
#define SMEM_GEMM_BYTES (4 * 4224 * 4)   // A0,A1,B0,B1 = 67584 B

// out[r][o] = sum_c act(A[r][c]) * W[o][c] + bias[o], K = 256.
// Tile 128x128, BK=32, 256 threads, 8 warps (2M x 4N).
// BN batch-stats (sum/sumsq per output channel) fused into the epilogue.
__global__ void __launch_bounds__(256)
gemm_mma_kernel(const float* __restrict__ A, const float* __restrict__ W,
                const float* __restrict__ bias, int useAct,
                float* __restrict__ out, int O) {
    extern __shared__ float sm[];
    float* As[2] = {sm,                sm + A_BUF_FLOATS};
    float* Bs[2] = {sm + 2*A_BUF_FLOATS, sm + 2*A_BUF_FLOATS + B_BUF_FLOATS};

    const int tid = threadIdx.x;
    const int lane = tid & 31, wid = tid >> 5;
    const int wm = wid >> 2, wn = wid & 3;
    const size_t rowBase = (size_t)blockIdx.x * 128;
    const int colBase = blockIdx.y * 128;

    // producer coords: idx = tid + 256*i ; row/col = idx>>3, k4 = idx&7
    const int prow = tid >> 3;          // 0..31 (+32*i)
    const int pk4  = tid & 7;           // float4 index within BK=32
    const float* aG = A + (rowBase + prow) * 256 + pk4 * 4;
    const float* wG = W + (size_t)(colBase + prow) * 256 + pk4 * 4;

    float acc[4][4][4];
    #pragma unroll
    for (int i = 0; i < 4; i++)
        #pragma unroll
        for (int j = 0; j < 4; j++)
            #pragma unroll
            for (int r = 0; r < 4; r++) acc[i][j][r] = 0.f;

    float4 va[4], vb[4];
    auto loadG = [&](int kb) {
        #pragma unroll
        for (int i = 0; i < 4; i++) {
            va[i] = *(const float4*)(aG + (size_t)(32 * i) * 256 + kb * 32);
            vb[i] = *(const float4*)(wG + (size_t)(32 * i) * 256 + kb * 32);
        }
    };
    auto storeS = [&](int s, int kb) {
        const int ks = pk4 >> 1;
        #pragma unroll
        for (int i = 0; i < 4; i++) {
            float4 v = va[i];
            if (useAct) {
                int c = kb * 32 + pk4 * 4;
                v.x = fmaxf(fmaf(v.x, g_scale[c + 0], g_shift[c + 0]), 0.f);
                v.y = fmaxf(fmaf(v.y, g_scale[c + 1], g_shift[c + 1]), 0.f);
                v.z = fmaxf(fmaf(v.z, g_scale[c + 2], g_shift[c + 2]), 0.f);
                v.w = fmaxf(fmaf(v.w, g_scale[c + 3], g_shift[c + 3]), 0.f);
            }
            // A scatter
            {
                int m = prow + 32 * i;
                int g = m >> 4, r16 = m & 15;
                int reg = (r16 >> 3) + ((pk4 & 1) << 1);
                int lbase = (r16 & 7) * 4;
                float* d = As[s] + g * 528 + ks * 132 + reg;
                uint32_t* du = (uint32_t*)d;
                du[(lbase + 0) * 4] = f2tf32(v.x);
                du[(lbase + 1) * 4] = f2tf32(v.y);
                du[(lbase + 2) * 4] = f2tf32(v.z);
                du[(lbase + 3) * 4] = f2tf32(v.w);
            }
            // B scatter
            {
                float4 w4 = vb[i];
                int n = prow + 32 * i;
                int h = n >> 3;
                int reg = pk4 & 1;
                int lbase = (n & 7) * 4;
                uint32_t* du = (uint32_t*)(Bs[s] + h * 264 + ks * 66 + reg);
                du[(lbase + 0) * 2] = f2tf32(w4.x);
                du[(lbase + 1) * 2] = f2tf32(w4.y);
                du[(lbase + 2) * 2] = f2tf32(w4.z);
                du[(lbase + 3) * 2] = f2tf32(w4.w);
            }
        }
    };

    loadG(0);
    storeS(0, 0);
    __syncthreads();

    for (int kb = 0; kb < 8; kb++) {
        const int s = kb & 1;
        if (kb < 7) loadG(kb + 1);
        #pragma unroll
        for (int ks = 0; ks < 4; ks++) {
            uint4 af[4]; uint2 bf[4];
            #pragma unroll
            for (int mt = 0; mt < 4; mt++)
                af[mt] = *(const uint4*)(As[s] + (wm * 4 + mt) * 528 + ks * 132 + lane * 4);
            #pragma unroll
            for (int nt = 0; nt < 4; nt++)
                bf[nt] = *(const uint2*)(Bs[s] + (wn * 4 + nt) * 264 + ks * 66 + lane * 2);
            #pragma unroll
            for (int mt = 0; mt < 4; mt++)
                #pragma unroll
                for (int nt = 0; nt < 4; nt++)
                    MMA_TF32(acc[mt][nt], af[mt], bf[nt]);
        }
        if (kb < 7) {
            storeS(s ^ 1, kb + 1);
            __syncthreads();
        }
    }

    // epilogue: +bias, store, fused per-channel stats
    float sp[8], ssp[8];
    #pragma unroll
    for (int c = 0; c < 8; c++) { sp[c] = 0.f; ssp[c] = 0.f; }

    const int gId = lane >> 2, l4 = lane & 3;
    #pragma unroll
    for (int mt = 0; mt < 4; mt++) {
        size_t row0 = rowBase + wm * 64 + mt * 16 + gId;
        #pragma unroll
        for (int nt = 0; nt < 4; nt++) {
            int col0 = colBase + wn * 32 + nt * 8 + 2 * l4;
            float b0 = bias[col0], b1 = bias[col0 + 1];
            float v00 = acc[mt][nt][0] + b0, v01 = acc[mt][nt][1] + b1;
            float v10 = acc[mt][nt][2] + b0, v11 = acc[mt][nt][3] + b1;
            *(float2*)(out + row0 * O + col0)        = make_float2(v00, v01);
            *(float2*)(out + (row0 + 8) * O + col0)  = make_float2(v10, v11);
            sp[nt * 2 + 0]  += v00 + v10;
            sp[nt * 2 + 1]  += v01 + v11;
            ssp[nt * 2 + 0] += v00 * v00 + v10 * v10;
            ssp[nt * 2 + 1] += v01 * v01 + v11 * v11;
        }
    }
    // reduce over groupID (lanes differing in bits 2..4)
    #pragma unroll
    for (int c = 0; c < 8; c++) {
        #pragma unroll
        for (int mask = 4; mask <= 16; mask <<= 1) {
            sp[c]  += __shfl_xor_sync(0xffffffffu, sp[c],  mask);
            ssp[c] += __shfl_xor_sync(0xffffffffu, ssp[c], mask);
        }
    }
    if (lane < 4) {
        #pragma unroll
        for (int nt = 0; nt < 4; nt++) {
            #pragma unroll
            for (int h = 0; h < 2; h++) {
                int col = colBase + wn * 32 + nt * 8 + 2 * lane + h;
                atomicAdd(&g_sum[col],   sp[nt * 2 + h]);
                atomicAdd(&g_sumsq[col], ssp[nt * 2 + h]);
            }
        }
    }
}

// ---------------------------------------------------------------------------
// fold BN into per-channel affine: scale = gamma*rsqrt(var+eps), shift = beta - mu*scale
__global__ void bn_finalize_kernel(const float* __restrict__ g,
                                   const float* __restrict__ beta, int O) {
    int t = threadIdx.x; // 256 threads always
    if (t < O) {
        const float cnt = (float)Rr;
        float mu  = g_sum[t] / cnt;
        float var = fmaxf(g_sumsq[t] / cnt - mu * mu, 0.f);
        float sc  = rsqrtf(var + BN_EPS) * g[t];
        g_scale[t] = sc;
        g_shift[t] = beta[t] - mu * sc;
    }
    g_sum[t] = 0.f; g_sumsq[t] = 0.f;
}

// ---------------------------------------------------------------------------
// final BN+ReLU + transpose [b][n][o] -> [b][o][n] into d_out (O = 128)
__global__ void output_kernel(const float* __restrict__ in, float* __restrict__ out) {
    __shared__ float t[32][33];
    const int b = blockIdx.z;
    const int n0 = blockIdx.x * 32, o0 = blockIdx.y * 32;
    const int tx = threadIdx.x, ty = threadIdx.y; // 32 x 8
    #pragma unroll
    for (int k = 0; k < 32; k += 8) {
        int o = o0 + tx;
        float v = in[((size_t)b * Np + n0 + ty + k) * 128 + o];
        t[ty + k][tx] = fmaxf(fmaf(v, g_scale[o], g_shift[o]), 0.f);
    }
    __syncthreads();
    #pragma unroll
    for (int k = 0; k < 32; k += 8)
        out[((size_t)b * 128 + o0 + ty + k) * Np + n0 + tx] = t[tx][ty + k];
}

// ---------------------------------------------------------------------------
extern "C" void kernel_launch(void* const* d_in, const int* in_sizes, int n_in,
                              void* d_out, int out_size) {
    const float* p   = (const float*)d_in[0];
    const float* q   = (const float*)d_in[1];
    const float* x   = (const float*)d_in[2];
    const float* w0  = (const float*)d_in[3];
    const float* b0  = (const float*)d_in[4];
    const float* g0  = (const float*)d_in[5];
    const float* be0 = (const float*)d_in[6];
    const float* w1  = (const float*)d_in[7];
    const float* b1  = (const float*)d_in[8];
    const float* g1  = (const float*)d_in[9];
    const float* be1 = (const float*)d_in[10];
    const float* w2  = (const float*)d_in[11];
    const float* b2  = (const float*)d_in[12];
    const float* g2  = (const float*)d_in[13];
    const float* be2 = (const float*)d_in[14];
    float* out = (float*)d_out;

    float *bufA, *bufB, *xT;
    cudaGetSymbolAddress((void**)&bufA, g_bufA);
    cudaGetSymbolAddress((void**)&bufB, g_bufB);
    cudaGetSymbolAddress((void**)&xT,  g_xT);

    const int Qfloats = Bb * Mp * 3;                    // 24576
    const int Hfloats = Bb * 128 * Np;                  // 8388608
    const int qoff = (out_size >= Qfloats + Hfloats) ? Qfloats : 0;

    cudaFuncSetAttribute(gemm_mma_kernel,
                         cudaFuncAttributeMaxDynamicSharedMemorySize, SMEM_GEMM_BYTES);

    zero_stats_kernel<<<1, 256>>>();
    transpose_x_kernel<<<dim3(Mp / 32, Cc / 32, Bb), dim3(32, 8)>>>(x, xT);
    knn_interp_kernel<<<dim3(Bb, Np / 128), 128>>>(p, q, xT, bufA);

    // layer 0: in bufA (raw), out bufB (256 ch) — stats fused
    gemm_mma_kernel<<<dim3(Rr / 128, 2), 256, SMEM_GEMM_BYTES>>>(bufA, w0, b0, 0, bufB, 256);
    bn_finalize_kernel<<<1, 256>>>(g0, be0, 256);

    // layer 1: in bufB (BN0+ReLU fused on load), out bufA (256 ch)
    gemm_mma_kernel<<<dim3(Rr / 128, 2), 256, SMEM_GEMM_BYTES>>>(bufB, w1, b1, 1, bufA, 256);
    bn_finalize_kernel<<<1, 256>>>(g1, be1, 256);

    // layer 2: in bufA (BN1+ReLU fused on load), out bufB (128 ch)
    gemm_mma_kernel<<<dim3(Rr / 128, 1), 256, SMEM_GEMM_BYTES>>>(bufA, w2, b2, 1, bufB, 128);
    bn_finalize_kernel<<<1, 256>>>(g2, be2, 128);

    // output: [q | BN2+ReLU(h) transposed to [B,128,N]]
    if (qoff)
        cudaMemcpyAsync(out, q, (size_t)Qfloats * sizeof(float),
                        cudaMemcpyDeviceToDevice);
    output_kernel<<<dim3(Np / 32, 4, Bb), dim3(32, 8)>>>(bufB, out + qoff);
}

// round 5
// speedup vs baseline: 1.9950x; 1.0693x over previous
#include <cuda_runtime.h>
#include <cstddef>
#include <cstdint>

// Problem constants
#define Bb 8
#define Np 8192
#define Mp 1024
#define Cc 256
#define Rr (Bb*Np)       // 65536 rows
#define BN_EPS 1e-5f

// Scratch (static __device__ — no allocations allowed)
__device__ float g_bufA[(size_t)Rr*Cc];     // 64 MB
__device__ float g_bufB[(size_t)Rr*Cc];     // 64 MB
__device__ float g_xT[(size_t)Bb*Mp*Cc];    // 8 MB
__device__ float g_sum[Cc];
__device__ float g_sumsq[Cc];
__device__ float g_scale[Cc];
__device__ float g_shift[Cc];

// ---------------------------------------------------------------------------
__global__ void zero_stats_kernel() {
    int t = threadIdx.x;
    g_sum[t] = 0.f; g_sumsq[t] = 0.f;
}

// ---------------------------------------------------------------------------
// transpose x[b][c][m] -> xT[b][m][c]
__global__ void transpose_x_kernel(const float* __restrict__ x, float* __restrict__ xT) {
    __shared__ float t[32][33];
    int b = blockIdx.z;
    int m0 = blockIdx.x * 32, c0 = blockIdx.y * 32;
    int tx = threadIdx.x, ty = threadIdx.y; // 32 x 8
    const float* xb = x + (size_t)b * Cc * Mp;
    #pragma unroll
    for (int k = 0; k < 32; k += 8)
        t[ty + k][tx] = xb[(size_t)(c0 + ty + k) * Mp + m0 + tx];
    __syncthreads();
    float* ob = xT + (size_t)b * Mp * Cc;
    #pragma unroll
    for (int k = 0; k < 32; k += 8)
        ob[(size_t)(m0 + ty + k) * Cc + c0 + tx] = t[tx][ty + k];
}

// ---------------------------------------------------------------------------
// 3-NN + inverse-distance-weighted interpolation. Writes h0 in [b][n][c].
__global__ void knn_interp_kernel(const float* __restrict__ p,
                                  const float* __restrict__ q,
                                  const float* __restrict__ xT,
                                  float* __restrict__ h0) {
    __shared__ float sqx[Mp], sqy[Mp], sqz[Mp], sqq[Mp];
    __shared__ float sw[128][3];
    __shared__ int   si[128][3];
    const int b = blockIdx.x;
    const int n0 = blockIdx.y * 128;
    const int tid = threadIdx.x;

    for (int m = tid; m < Mp; m += 128) {
        float qx = q[((size_t)b * Mp + m) * 3 + 0];
        float qy = q[((size_t)b * Mp + m) * 3 + 1];
        float qz = q[((size_t)b * Mp + m) * 3 + 2];
        sqx[m] = qx; sqy[m] = qy; sqz[m] = qz;
        sqq[m] = qx * qx + qy * qy + qz * qz;
    }
    __syncthreads();

    const int n = n0 + tid;
    float px = p[((size_t)b * Np + n) * 3 + 0];
    float py = p[((size_t)b * Np + n) * 3 + 1];
    float pz = p[((size_t)b * Np + n) * 3 + 2];
    float pp = px * px + py * py + pz * pz;

    float d0 = 3.4e38f, d1 = 3.4e38f, d2v = 3.4e38f;
    int   i0 = 0, i1 = 0, i2 = 0;
    #pragma unroll 4
    for (int m = 0; m < Mp; m++) {
        float dot = px * sqx[m] + py * sqy[m] + pz * sqz[m];
        float d = pp + sqq[m] - 2.f * dot;
        if (d < d2v) {
            if (d < d1) {
                d2v = d1; i2 = i1;
                if (d < d0) { d1 = d0; i1 = i0; d0 = d; i0 = m; }
                else        { d1 = d;  i1 = m; }
            } else { d2v = d; i2 = m; }
        }
    }
    float a0 = 1.f / fmaxf(d0, 1e-10f);
    float a1 = 1.f / fmaxf(d1, 1e-10f);
    float a2 = 1.f / fmaxf(d2v, 1e-10f);
    float inv = 1.f / (a0 + a1 + a2);
    sw[tid][0] = a0 * inv; sw[tid][1] = a1 * inv; sw[tid][2] = a2 * inv;
    si[tid][0] = i0; si[tid][1] = i1; si[tid][2] = i2;
    __syncthreads();

    const int lane = tid & 31, warp = tid >> 5;
    const float* xb = xT + (size_t)b * Mp * Cc;
    for (int nl = warp * 32; nl < warp * 32 + 32; nl++) {
        float w0 = sw[nl][0], w1 = sw[nl][1], w2 = sw[nl][2];
        const float* r0 = xb + (size_t)si[nl][0] * Cc;
        const float* r1 = xb + (size_t)si[nl][1] * Cc;
        const float* r2 = xb + (size_t)si[nl][2] * Cc;
        float* o = h0 + ((size_t)b * Np + n0 + nl) * Cc;
        #pragma unroll
        for (int c = lane; c < Cc; c += 32)
            o[c] = w0 * r0[c] + w1 * r1[c] + w2 * r2[c];
    }
}

// ---------------------------------------------------------------------------
// bf16x3 emulated-fp32 GEMM via legacy mma.sync (sm_80 PTX path)
// ---------------------------------------------------------------------------
__device__ __forceinline__ uint32_t prmt_hi(uint32_t a, uint32_t b) {
    uint32_t r; asm("prmt.b32 %0, %1, %2, 0x7632;" : "=r"(r) : "r"(a), "r"(b));
    return r;   // {lo16 = a.hi16, hi16 = b.hi16}
}
__device__ __forceinline__ uint32_t pack_bf16_rn(float lo0, float lo1) {
    uint32_t r; asm("cvt.rn.bf16x2.f32 %0, %1, %2;" : "=r"(r) : "f"(lo1), "f"(lo0));
    return r;   // low half = lo0
}
__device__ __forceinline__ float trunc_hi_f(float f) {
    return __uint_as_float(__float_as_uint(f) & 0xFFFF0000u);
}

#define MMA_BF16(c, a, b0v, b1v) \
    asm volatile("mma.sync.aligned.m16n8k16.row.col.f32.bf16.bf16.f32 " \
        "{%0,%1,%2,%3},{%4,%5,%6,%7},{%8,%9},{%0,%1,%2,%3};" \
        : "+f"((c)[0]), "+f"((c)[1]), "+f"((c)[2]), "+f"((c)[3]) \
        : "r"((a).x), "r"((a).y), "r"((a).z), "r"((a).w), "r"(b0v), "r"(b1v))

#define LDMATRIX_X4(r, addr) \
    asm volatile("ldmatrix.sync.aligned.m8n8.x4.shared.b16 {%0,%1,%2,%3}, [%4];" \
        : "=r"((r).x), "=r"((r).y), "=r"((r).z), "=r"((r).w) : "r"(addr))

// smem tiles: bf16, row-major, 128 rows x 32 k = 64 B/row, XOR-granule swizzle.
// addr(row, kg) = row*64 + (kg ^ ((row>>1)&3))*16        (kg = 16B granule 0..3)
#define TILE_B   8192                 // one 128x32 bf16 tile
#define STAGE_B  (4 * TILE_B)         // A_hi, A_lo, B_hi, B_lo
#define SMEM_GEMM_BYTES (2 * STAGE_B) // 65536

// out[r][o] = sum_c act(A[r][c]) * W[o][c] + bias[o], K=256, tile 128x128.
// 512 threads, 16 warps (4M x 4N). BN stats fused into epilogue.
__global__ void __launch_bounds__(512)
gemm_bf16x3_kernel(const float* __restrict__ A, const float* __restrict__ W,
                   const float* __restrict__ bias, int useAct,
                   float* __restrict__ out, int O) {
    extern __shared__ char smc[];
    const int tid = threadIdx.x;
    const int lane = tid & 31, wid = tid >> 5;
    const int wm = wid >> 2, wn = wid & 3;
    const size_t rowBase = (size_t)blockIdx.x * 128;
    const int colBase = blockIdx.y * 128;

    const uint32_t smb = (uint32_t)__cvta_generic_to_shared(smc);
    // stage s base: smb + s*STAGE_B; tiles: A_hi +0, A_lo +TILE_B, B_hi +2*, B_lo +3*

    // producer mapping: row = tid>>2 (0..127), kg = tid&3 (8 k each)
    const int prow = tid >> 2;
    const int pkg = tid & 3;
    const uint32_t pOff = (uint32_t)(prow * 64 + ((pkg ^ ((prow >> 1) & 3)) << 4));
    const float* aG = A + (rowBase + prow) * 256 + pkg * 8;
    const float* wG = W + (size_t)(colBase + prow) * 256 + pkg * 8;

    float acc[2][4][4];
    #pragma unroll
    for (int i = 0; i < 2; i++)
        #pragma unroll
        for (int j = 0; j < 4; j++)
            #pragma unroll
            for (int r = 0; r < 4; r++) acc[i][j][r] = 0.f;

    float4 va0, va1, vb0, vb1;
    auto loadG = [&](int kb) {
        va0 = *(const float4*)(aG + kb * 32);
        va1 = *(const float4*)(aG + kb * 32 + 4);
        vb0 = *(const float4*)(wG + kb * 32);
        vb1 = *(const float4*)(wG + kb * 32 + 4);
    };
    auto storeS = [&](int s, int kb) {
        uint32_t base = smb + s * STAGE_B + pOff;
        float a[8] = {va0.x, va0.y, va0.z, va0.w, va1.x, va1.y, va1.z, va1.w};
        if (useAct) {
            int c = kb * 32 + pkg * 8;
            #pragma unroll
            for (int j = 0; j < 8; j++)
                a[j] = fmaxf(fmaf(a[j], g_scale[c + j], g_shift[c + j]), 0.f);
        }
        uint4 hi, lo;
        hi.x = prmt_hi(__float_as_uint(a[0]), __float_as_uint(a[1]));
        hi.y = prmt_hi(__float_as_uint(a[2]), __float_as_uint(a[3]));
        hi.z = prmt_hi(__float_as_uint(a[4]), __float_as_uint(a[5]));
        hi.w = prmt_hi(__float_as_uint(a[6]), __float_as_uint(a[7]));
        lo.x = pack_bf16_rn(a[0] - trunc_hi_f(a[0]), a[1] - trunc_hi_f(a[1]));
        lo.y = pack_bf16_rn(a[2] - trunc_hi_f(a[2]), a[3] - trunc_hi_f(a[3]));
        lo.z = pack_bf16_rn(a[4] - trunc_hi_f(a[4]), a[5] - trunc_hi_f(a[5]));
        lo.w = pack_bf16_rn(a[6] - trunc_hi_f(a[6]), a[7] - trunc_hi_f(a[7]));
        asm volatile("st.shared.v4.b32 [%0], {%1,%2,%3,%4};"
                     :: "r"(base), "r"(hi.x), "r"(hi.y), "r"(hi.z), "r"(hi.w));
        asm volatile("st.shared.v4.b32 [%0], {%1,%2,%3,%4};"
                     :: "r"(base + TILE_B), "r"(lo.x), "r"(lo.y), "r"(lo.z), "r"(lo.w));

        float b[8] = {vb0.x, vb0.y, vb0.z, vb0.w, vb1.x, vb1.y, vb1.z, vb1.w};
        hi.x = prmt_hi(__float_as_uint(b[0]), __float_as_uint(b[1]));
        hi.y = prmt_hi(__float_as_uint(b[2]), __float_as_uint(b[3]));
        hi.z = prmt_hi(__float_as_uint(b[4]), __float_as_uint(b[5]));
        hi.w = prmt_hi(__float_as_uint(b[6]), __float_as_uint(b[7]));
        lo.x = pack_bf16_rn(b[0] - trunc_hi_f(b[0]), b[1] - trunc_hi_f(b[1]));
        lo.y = pack_bf16_rn(b[2] - trunc_hi_f(b[2]), b[3] - trunc_hi_f(b[3]));
        lo.z = pack_bf16_rn(b[4] - trunc_hi_f(b[4]), b[5] - trunc_hi_f(b[5]));
        lo.w = pack_bf16_rn(b[6] - trunc_hi_f(b[6]), b[7] - trunc_hi_f(b[7]));
        asm volatile("st.shared.v4.b32 [%0], {%1,%2,%3,%4};"
                     :: "r"(base + 2 * TILE_B), "r"(hi.x), "r"(hi.y), "r"(hi.z), "r"(hi.w));
        asm volatile("st.shared.v4.b32 [%0], {%1,%2,%3,%4};"
                     :: "r"(base + 3 * TILE_B), "r"(lo.x), "r"(lo.y), "r"(lo.z), "r"(lo.w));
    };

    // consumer per-lane ldmatrix row/granule precomputation
    // A x4: row = wm*32 + mt*16 + ((lane>>3)&1)*8 + (lane&7); khalf = (lane>>4)&1
    const int aRow0 = wm * 32 + ((lane >> 3) & 1) * 8 + (lane & 7);  // mt=0
    const int aKh = (lane >> 4) & 1;
    // B x4: row_n = wn*32 + (2p + ((lane>>4)&1))*8 + (lane&7); khalf = (lane>>3)&1
    const int bRow0 = wn * 32 + ((lane >> 4) & 1) * 8 + (lane & 7);  // p=0
    const int bKh = (lane >> 3) & 1;

    loadG(0);
    storeS(0, 0);
    __syncthreads();

    for (int kb = 0; kb < 8; kb++) {
        const int s = kb & 1;
        if (kb < 7) loadG(kb + 1);
        const uint32_t stA = smb + s * STAGE_B;
        const uint32_t stB = stA + 2 * TILE_B;
        #pragma unroll
        for (int ks = 0; ks < 2; ks++) {
            uint4 ah[2], al[2], bh[2], bl[2];
            #pragma unroll
            for (int mt = 0; mt < 2; mt++) {
                int row = aRow0 + mt * 16;
                uint32_t ad = stA + row * 64 + ((((ks << 1) + aKh) ^ ((row >> 1) & 3)) << 4);
                LDMATRIX_X4(ah[mt], ad);
                LDMATRIX_X4(al[mt], ad + TILE_B);
            }
            #pragma unroll
            for (int p = 0; p < 2; p++) {
                int row = bRow0 + p * 16;
                uint32_t bd = stB + row * 64 + ((((ks << 1) + bKh) ^ ((row >> 1) & 3)) << 4);
                LDMATRIX_X4(bh[p], bd);
                LDMATRIX_X4(bl[p], bd + TILE_B);
            }
            #pragma unroll
            for (int mt = 0; mt < 2; mt++) {
                #pragma unroll
                for (int p = 0; p < 2; p++) {
                    // nt = 2p: regs (x,y); nt = 2p+1: regs (z,w)
                    MMA_BF16(acc[mt][2*p],   ah[mt], bh[p].x, bh[p].y);
                    MMA_BF16(acc[mt][2*p],   ah[mt], bl[p].x, bl[p].y);
                    MMA_BF16(acc[mt][2*p],   al[mt], bh[p].x, bh[p].y);
                    MMA_BF16(acc[mt][2*p+1], ah[mt], bh[p].z, bh[p].w);
                    MMA_BF16(acc[mt][2*p+1], ah[mt], bl[p].z, bl[p].w);
                    MMA_BF16(acc[mt][2*p+1], al[mt], bh[p].z, bh[p].w);
                }
            }
        }
        if (kb < 7) {
            storeS(s ^ 1, kb + 1);
            __syncthreads();
        }
    }

    // epilogue: +bias, store, fused per-channel stats
    float sp[8], ssp[8];
    #pragma unroll
    for (int c = 0; c < 8; c++) { sp[c] = 0.f; ssp[c] = 0.f; }

    const int gId = lane >> 2, l4 = lane & 3;
    #pragma unroll
    for (int mt = 0; mt < 2; mt++) {
        size_t row0 = rowBase + wm * 32 + mt * 16 + gId;
        #pragma unroll
        for (int nt = 0; nt < 4; nt++) {
            int col0 = colBase + wn * 32 + nt * 8 + 2 * l4;
            float b0 = bias[col0], b1 = bias[col0 + 1];
            float v00 = acc[mt][nt][0] + b0, v01 = acc[mt][nt][1] + b1;
            float v10 = acc[mt][nt][2] + b0, v11 = acc[mt][nt][3] + b1;
            *(float2*)(out + row0 * O + col0)        = make_float2(v00, v01);
            *(float2*)(out + (row0 + 8) * O + col0)  = make_float2(v10, v11);
            sp[nt * 2 + 0]  += v00 + v10;
            sp[nt * 2 + 1]  += v01 + v11;
            ssp[nt * 2 + 0] += v00 * v00 + v10 * v10;
            ssp[nt * 2 + 1] += v01 * v01 + v11 * v11;
        }
    }
    #pragma unroll
    for (int c = 0; c < 8; c++) {
        #pragma unroll
        for (int mask = 4; mask <= 16; mask <<= 1) {
            sp[c]  += __shfl_xor_sync(0xffffffffu, sp[c],  mask);
            ssp[c] += __shfl_xor_sync(0xffffffffu, ssp[c], mask);
        }
    }
    if (lane < 4) {
        #pragma unroll
        for (int nt = 0; nt < 4; nt++) {
            #pragma unroll
            for (int h = 0; h < 2; h++) {
                int col = colBase + wn * 32 + nt * 8 + 2 * lane + h;
                atomicAdd(&g_sum[col],   sp[nt * 2 + h]);
                atomicAdd(&g_sumsq[col], ssp[nt * 2 + h]);
            }
        }
    }
}

// ---------------------------------------------------------------------------
// fold BN into per-channel affine: scale = gamma*rsqrt(var+eps), shift = beta - mu*scale
__global__ void bn_finalize_kernel(const float* __restrict__ g,
                                   const float* __restrict__ beta, int O) {
    int t = threadIdx.x; // 256 threads always
    if (t < O) {
        const float cnt = (float)Rr;
        float mu  = g_sum[t] / cnt;
        float var = fmaxf(g_sumsq[t] / cnt - mu * mu, 0.f);
        float sc  = rsqrtf(var + BN_EPS) * g[t];
        g_scale[t] = sc;
        g_shift[t] = beta[t] - mu * sc;
    }
    g_sum[t] = 0.f; g_sumsq[t] = 0.f;
}

// ---------------------------------------------------------------------------
// final BN+ReLU + transpose [b][n][o] -> [b][o][n] into d_out (O = 128)
__global__ void output_kernel(const float* __restrict__ in, float* __restrict__ out) {
    __shared__ float t[32][33];
    const int b = blockIdx.z;
    const int n0 = blockIdx.x * 32, o0 = blockIdx.y * 32;
    const int tx = threadIdx.x, ty = threadIdx.y; // 32 x 8
    #pragma unroll
    for (int k = 0; k < 32; k += 8) {
        int o = o0 + tx;
        float v = in[((size_t)b * Np + n0 + ty + k) * 128 + o];
        t[ty + k][tx] = fmaxf(fmaf(v, g_scale[o], g_shift[o]), 0.f);
    }
    __syncthreads();
    #pragma unroll
    for (int k = 0; k < 32; k += 8)
        out[((size_t)b * 128 + o0 + ty + k) * Np + n0 + tx] = t[tx][ty + k];
}

// ---------------------------------------------------------------------------
extern "C" void kernel_launch(void* const* d_in, const int* in_sizes, int n_in,
                              void* d_out, int out_size) {
    const float* p   = (const float*)d_in[0];
    const float* q   = (const float*)d_in[1];
    const float* x   = (const float*)d_in[2];
    const float* w0  = (const float*)d_in[3];
    const float* b0  = (const float*)d_in[4];
    const float* g0  = (const float*)d_in[5];
    const float* be0 = (const float*)d_in[6];
    const float* w1  = (const float*)d_in[7];
    const float* b1  = (const float*)d_in[8];
    const float* g1  = (const float*)d_in[9];
    const float* be1 = (const float*)d_in[10];
    const float* w2  = (const float*)d_in[11];
    const float* b2  = (const float*)d_in[12];
    const float* g2  = (const float*)d_in[13];
    const float* be2 = (const float*)d_in[14];
    float* out = (float*)d_out;

    float *bufA, *bufB, *xT;
    cudaGetSymbolAddress((void**)&bufA, g_bufA);
    cudaGetSymbolAddress((void**)&bufB, g_bufB);
    cudaGetSymbolAddress((void**)&xT,  g_xT);

    const int Qfloats = Bb * Mp * 3;                    // 24576
    const int Hfloats = Bb * 128 * Np;                  // 8388608
    const int qoff = (out_size >= Qfloats + Hfloats) ? Qfloats : 0;

    cudaFuncSetAttribute(gemm_bf16x3_kernel,
                         cudaFuncAttributeMaxDynamicSharedMemorySize, SMEM_GEMM_BYTES);

    zero_stats_kernel<<<1, 256>>>();
    transpose_x_kernel<<<dim3(Mp / 32, Cc / 32, Bb), dim3(32, 8)>>>(x, xT);
    knn_interp_kernel<<<dim3(Bb, Np / 128), 128>>>(p, q, xT, bufA);

    // layer 0: in bufA (raw), out bufB (256 ch) — stats fused
    gemm_bf16x3_kernel<<<dim3(Rr / 128, 2), 512, SMEM_GEMM_BYTES>>>(bufA, w0, b0, 0, bufB, 256);
    bn_finalize_kernel<<<1, 256>>>(g0, be0, 256);

    // layer 1: in bufB (BN0+ReLU fused on load), out bufA (256 ch)
    gemm_bf16x3_kernel<<<dim3(Rr / 128, 2), 512, SMEM_GEMM_BYTES>>>(bufB, w1, b1, 1, bufA, 256);
    bn_finalize_kernel<<<1, 256>>>(g1, be1, 256);

    // layer 2: in bufA (BN1+ReLU fused on load), out bufB (128 ch)
    gemm_bf16x3_kernel<<<dim3(Rr / 128, 1), 512, SMEM_GEMM_BYTES>>>(bufA, w2, b2, 1, bufB, 128);
    bn_finalize_kernel<<<1, 256>>>(g2, be2, 128);

    // output: [q | BN2+ReLU(h) transposed to [B,128,N]]
    if (qoff)
        cudaMemcpyAsync(out, q, (size_t)Qfloats * sizeof(float),
                        cudaMemcpyDeviceToDevice);
    output_kernel<<<dim3(Np / 32, 4, Bb), dim3(32, 8)>>>(bufB, out + qoff);
}